// round 13
// baseline (speedup 1.0000x reference)
#include <cuda_runtime.h>
#include <math.h>

#define IMAGE_W 256
#define IMAGE_H 256
#define EPS 1e-7f
#define SIGMA2 0.02f

#define B 16
#define N 64
#define C 3
#define PH 32
#define PW 32
#define TILE 32
#define PSZ (C*PH*PW)   // 3072 floats per stroke patch
#define SLOTS 3         // smem-staged survivor patches per chunk

// Fused kernel: one block per (batch, 32x32 tile), 512 threads.
// Warp 0: params + survivor compaction (1 barrier). Then chunks of <=3
// survivors: bulk coalesced copy of needed patch rows to smem, barrier,
// conflict-free LDS gather. Thread owns 1 col x 2 rows x 3 channels.
__global__ void __launch_bounds__(512) brush_kernel(
    const float* __restrict__ brushes,   // [B, N, 2]
    const float* __restrict__ patches,   // [B, N, 3, 32, 32]
    float* __restrict__ out)             // [B, 3, 256, 256]
{
    const int bt   = blockIdx.x;         // b*64 + tile
    const int b    = bt >> 6;
    const int tile = bt & 63;
    const int tx0  = (tile & 7) * TILE;
    const int ty0  = (tile >> 3) * TILE;
    const int tid  = threadIdx.x;
    const int lx   = tid & 31;
    const int g    = tid >> 5;           // 0..15

    __shared__ int4   cmeta[N];          // fx, fy, patch float-offset, pad
    __shared__ float4 cw[N];             // wx0, wx1, wy0/64, wy1/64
    __shared__ int    s_cnt;
    __shared__ alignas(16) float sPat[SLOTS][C][PH][PW];   // 36 KB staging

    // ---- warp-0 prologue: params for 2 strokes/lane, ballot-compact ----
    if (tid < 32) {
        const int l = tid;
        const float2 br0 = ((const float2*)brushes)[b * N + l];
        const float2 br1 = ((const float2*)brushes)[b * N + l + 32];

        float mnx = fminf(br0.x, br1.x), mxx = fmaxf(br0.x, br1.x);
        float mny = fminf(br0.y, br1.y), mxy = fmaxf(br0.y, br1.y);
#pragma unroll
        for (int o = 16; o > 0; o >>= 1) {
            mnx = fminf(mnx, __shfl_xor_sync(0xffffffffu, mnx, o));
            mxx = fmaxf(mxx, __shfl_xor_sync(0xffffffffu, mxx, o));
            mny = fminf(mny, __shfl_xor_sync(0xffffffffu, mny, o));
            mxy = fmaxf(mxy, __shfl_xor_sync(0xffffffffu, mxy, o));
        }
        const float isx = 1.0f / (mxx - mnx + EPS) * (float)IMAGE_W;
        const float isy = 1.0f / (mxy - mny + EPS) * (float)IMAGE_H;

        int    fx[2], fy[2];
        float4 wt[2];
        bool   ov[2];
#pragma unroll
        for (int k = 0; k < 2; k++) {
            const float bx = k ? br1.x : br0.x;
            const float by = k ? br1.y : br0.y;
            const float axc = (bx - mnx) * isx - 15.5f;  // ux(q)=gx+q-15.5
            const float fx0f = floorf(axc);
            const float dx = axc - fx0f;
            const float ayc = (by - mny) * isy - 15.4f;  // uy(p)=gy+p-15.4
            const float fy0f = floorf(ayc);
            const float dy = ayc - fy0f;

            const float gx0 = __expf(-(dx * dx) / SIGMA2);
            const float gx1 = __expf(-((1.0f - dx) * (1.0f - dx)) / SIGMA2);
            const float wx0 = gx0 / (gx0 + gx1 + EPS);
            const float wx1 = gx1 / (gx0 + gx1 + EPS);

            const float gy0 = __expf(-(dy * dy) / SIGMA2);
            const float gy1 = __expf(-((1.0f - dy) * (1.0f - dy)) / SIGMA2);
            const float s  = 1.0f / 64.0f;               // fold /N into wy
            const float wy0 = gy0 / (gy0 + gy1 + EPS) * s;
            const float wy1 = gy1 / (gy0 + gy1 + EPS) * s;

            fx[k] = (int)fx0f;
            fy[k] = (int)fy0f;
            wt[k] = make_float4(wx0, wx1, wy0, wy1);
            ov[k] = !(fx[k] > tx0 + 31 || fx[k] + 32 < tx0 ||
                      fy[k] > ty0 + 31 || fy[k] + 32 < ty0);
        }

        const unsigned m0 = __ballot_sync(0xffffffffu, ov[0]);
        const unsigned m1 = __ballot_sync(0xffffffffu, ov[1]);
        const unsigned ltm = (1u << l) - 1u;
        const int base1 = __popc(m0);
        if (ov[0]) {
            const int pos = __popc(m0 & ltm);
            cmeta[pos] = make_int4(fx[0], fy[0], (b * N + l) * PSZ, 0);
            cw[pos]    = wt[0];
        }
        if (ov[1]) {
            const int pos = base1 + __popc(m1 & ltm);
            cmeta[pos] = make_int4(fx[1], fy[1], (b * N + l + 32) * PSZ, 0);
            cw[pos]    = wt[1];
        }
        if (l == 0) s_cnt = base1 + __popc(m1);
    }
    __syncthreads();
    const int cnt = s_cnt;

    const int x     = tx0 + lx;
    const int ybase = ty0 + g * 2;       // rows ybase, ybase+1

    float acc[C][2];
#pragma unroll
    for (int c = 0; c < C; c++) { acc[c][0] = 0.0f; acc[c][1] = 0.0f; }

    for (int s0 = 0; s0 < cnt; s0 += SLOTS) {
        const int m = min(SLOTS, cnt - s0);
        if (s0 > 0) __syncthreads();     // previous chunk's readers done

        // ---- bulk copy: needed row-range of each survivor patch -> smem ----
        for (int k = 0; k < m; k++) {
            const int4 md = cmeta[s0 + k];
            const int r0  = max(0, ty0 - md.y - 1);
            const int r1  = min(31, ty0 - md.y + 32);
            const int nr8 = (r1 - r0 + 1) << 3;      // float4 per channel
            const float4* src = (const float4*)(patches + md.z);
            float4* dst = (float4*)&sPat[k][0][0][0];
            for (int t = tid; t < C * nr8; t += 512) {
                const int c   = t / nr8;
                const int rem = t - c * nr8;
                const int idx = (c << 8) + (r0 << 3) + rem;  // same layout
                dst[idx] = src[idx];
            }
        }
        __syncthreads();

        // ---- gather from smem (conflict-free: i consecutive per lane) ----
        for (int k = 0; k < m; k++) {
            const int4   md = cmeta[s0 + k];
            const float4 wt = cw[s0 + k];
            const int i  = x - md.x;                   // window col
            const int jb = ybase - md.y;               // warp-uniform row
            if (jb < -1 || jb > 32) continue;          // warp-uniform skip
            const bool c0 = ((unsigned)i       < 32u);
            const bool c1 = ((unsigned)(i - 1) < 32u);
#pragma unroll
            for (int c = 0; c < C; c++) {
                const float* Pc = &sPat[k][c][0][0];
                float h[3];
#pragma unroll
                for (int r = 0; r < 3; r++) {
                    const int rr = jb - 1 + r;
                    const bool rv = ((unsigned)rr < 32u);
                    const float p0 = (rv & c0) ? Pc[(rr << 5) + i]     : 0.0f;
                    const float p1 = (rv & c1) ? Pc[(rr << 5) + i - 1] : 0.0f;
                    h[r] = wt.x * p0 + wt.y * p1;
                }
                acc[c][0] += wt.z * h[1] + wt.w * h[0];
                acc[c][1] += wt.z * h[2] + wt.w * h[1];
            }
        }
    }

    // ---- coalesced stores: [b][c][y][x] ----
#pragma unroll
    for (int c = 0; c < C; c++) {
        float* oc = out + ((size_t)(b * C + c) * IMAGE_H) * IMAGE_W;
        oc[(size_t)(ybase    ) * IMAGE_W + x] = acc[c][0];
        oc[(size_t)(ybase + 1) * IMAGE_W + x] = acc[c][1];
    }
}

extern "C" void kernel_launch(void* const* d_in, const int* in_sizes, int n_in,
                              void* d_out, int out_size)
{
    const float* brushes = (const float*)d_in[0];   // [16,64,2]
    const float* patches = (const float*)d_in[1];   // [16,64,3,32,32]
    float* out = (float*)d_out;                     // [16,3,256,256]

    brush_kernel<<<B * 64, 512>>>(brushes, patches, out);
}

// round 14
// speedup vs baseline: 1.2129x; 1.2129x over previous
#include <cuda_runtime.h>
#include <math.h>

#define IMAGE_W 256
#define IMAGE_H 256
#define EPS 1e-7f
#define SIGMA2 0.02f

#define B 16
#define N 64
#define C 3
#define PH 32
#define PW 32
#define TILE 32
#define PSZ (C*PH*PW)   // 3072 floats per stroke patch

// Fused kernel: one block per (batch, 32x32 tile), 256 threads.
// Warp 0 computes stroke params + compacts tile survivors (1 barrier);
// then each thread gathers 1 col x 4 rows x 3 channels via the separable
// 2-tap filter (5 shared h-rows per 4 outputs), direct predicated LDGs.
__global__ void __launch_bounds__(256) brush_kernel(
    const float* __restrict__ brushes,   // [B, N, 2]
    const float* __restrict__ patches,   // [B, N, 3, 32, 32]
    float* __restrict__ out)             // [B, 3, 256, 256]
{
    const int bt   = blockIdx.x;         // b*64 + tile
    const int b    = bt >> 6;
    const int tile = bt & 63;
    const int tx0  = (tile & 7) * TILE;
    const int ty0  = (tile >> 3) * TILE;
    const int tid  = threadIdx.x;
    const int lx   = tid & 31;
    const int g    = tid >> 5;           // 0..7

    __shared__ int4   cmeta[N];          // fx, fy, patch float-offset, pad
    __shared__ float4 cw[N];             // wx0, wx1, wy0/64, wy1/64
    __shared__ int    s_cnt;

    // ---- warp-0 prologue: params for 2 strokes/lane, ballot-compact ----
    if (tid < 32) {
        const int l = tid;
        const float2 br0 = ((const float2*)brushes)[b * N + l];
        const float2 br1 = ((const float2*)brushes)[b * N + l + 32];

        float mnx = fminf(br0.x, br1.x), mxx = fmaxf(br0.x, br1.x);
        float mny = fminf(br0.y, br1.y), mxy = fmaxf(br0.y, br1.y);
#pragma unroll
        for (int o = 16; o > 0; o >>= 1) {
            mnx = fminf(mnx, __shfl_xor_sync(0xffffffffu, mnx, o));
            mxx = fmaxf(mxx, __shfl_xor_sync(0xffffffffu, mxx, o));
            mny = fminf(mny, __shfl_xor_sync(0xffffffffu, mny, o));
            mxy = fmaxf(mxy, __shfl_xor_sync(0xffffffffu, mxy, o));
        }
        const float isx = 1.0f / (mxx - mnx + EPS) * (float)IMAGE_W;
        const float isy = 1.0f / (mxy - mny + EPS) * (float)IMAGE_H;

        int    fx[2], fy[2];
        float4 wt[2];
        bool   ov[2];
#pragma unroll
        for (int k = 0; k < 2; k++) {
            const float bx = k ? br1.x : br0.x;
            const float by = k ? br1.y : br0.y;
            const float axc = (bx - mnx) * isx - 15.5f;  // ux(q)=gx+q-15.5
            const float fx0f = floorf(axc);
            const float dx = axc - fx0f;
            const float ayc = (by - mny) * isy - 15.4f;  // uy(p)=gy+p-15.4
            const float fy0f = floorf(ayc);
            const float dy = ayc - fy0f;

            const float gx0 = __expf(-(dx * dx) / SIGMA2);
            const float gx1 = __expf(-((1.0f - dx) * (1.0f - dx)) / SIGMA2);
            const float wx0 = gx0 / (gx0 + gx1 + EPS);
            const float wx1 = gx1 / (gx0 + gx1 + EPS);

            const float gy0 = __expf(-(dy * dy) / SIGMA2);
            const float gy1 = __expf(-((1.0f - dy) * (1.0f - dy)) / SIGMA2);
            const float s  = 1.0f / 64.0f;               // fold /N into wy
            const float wy0 = gy0 / (gy0 + gy1 + EPS) * s;
            const float wy1 = gy1 / (gy0 + gy1 + EPS) * s;

            fx[k] = (int)fx0f;
            fy[k] = (int)fy0f;
            wt[k] = make_float4(wx0, wx1, wy0, wy1);
            ov[k] = !(fx[k] > tx0 + 31 || fx[k] + 32 < tx0 ||
                      fy[k] > ty0 + 31 || fy[k] + 32 < ty0);
        }

        const unsigned m0 = __ballot_sync(0xffffffffu, ov[0]);
        const unsigned m1 = __ballot_sync(0xffffffffu, ov[1]);
        const unsigned ltm = (1u << l) - 1u;
        const int base1 = __popc(m0);
        if (ov[0]) {
            const int pos = __popc(m0 & ltm);
            cmeta[pos] = make_int4(fx[0], fy[0], (b * N + l) * PSZ, 0);
            cw[pos]    = wt[0];
        }
        if (ov[1]) {
            const int pos = base1 + __popc(m1 & ltm);
            cmeta[pos] = make_int4(fx[1], fy[1], (b * N + l + 32) * PSZ, 0);
            cw[pos]    = wt[1];
        }
        if (l == 0) s_cnt = base1 + __popc(m1);
    }
    __syncthreads();
    const int cnt = s_cnt;

    // ---- gather: 1 col x 4 rows x 3 channels per thread ----
    const int x     = tx0 + lx;
    const int ybase = ty0 + g * 4;       // rows ybase..ybase+3

    float acc[C][4];
#pragma unroll
    for (int c = 0; c < C; c++)
#pragma unroll
        for (int k = 0; k < 4; k++) acc[c][k] = 0.0f;

#pragma unroll 2
    for (int s = 0; s < cnt; s++) {
        const int4   md = cmeta[s];
        const float4 wt = cw[s];
        const int i  = x - md.x;                   // window col
        const int jb = ybase - md.y;               // window row of first output
        if (jb < -3 || jb > 32) continue;          // warp-uniform skip
        const bool c0 = ((unsigned)i       < 32u); // tap col i
        const bool c1 = ((unsigned)(i - 1) < 32u); // tap col i-1
        const float* Pn = patches + md.z + i;
#pragma unroll
        for (int c = 0; c < C; c++) {
            const float* Pc = Pn + c * (PH * PW);
            float h[5];                            // x-filtered rows jb-1..jb+3
#pragma unroll
            for (int r = 0; r < 5; r++) {
                const int rr = jb - 1 + r;
                const bool rv = ((unsigned)rr < 32u);
                const float p0 = (rv & c0) ? __ldg(Pc + rr * PW)     : 0.0f;
                const float p1 = (rv & c1) ? __ldg(Pc + rr * PW - 1) : 0.0f;
                h[r] = wt.x * p0 + wt.y * p1;
            }
#pragma unroll
            for (int k = 0; k < 4; k++)
                acc[c][k] += wt.z * h[k + 1] + wt.w * h[k];
        }
    }

    // ---- coalesced stores: [b][c][y][x] ----
#pragma unroll
    for (int c = 0; c < C; c++) {
        float* oc = out + ((size_t)(b * C + c) * IMAGE_H) * IMAGE_W;
#pragma unroll
        for (int k = 0; k < 4; k++)
            oc[(size_t)(ybase + k) * IMAGE_W + x] = acc[c][k];
    }
}

extern "C" void kernel_launch(void* const* d_in, const int* in_sizes, int n_in,
                              void* d_out, int out_size)
{
    const float* brushes = (const float*)d_in[0];   // [16,64,2]
    const float* patches = (const float*)d_in[1];   // [16,64,3,32,32]
    float* out = (float*)d_out;                     // [16,3,256,256]

    brush_kernel<<<B * 64, 256>>>(brushes, patches, out);
}

// round 15
// speedup vs baseline: 1.5117x; 1.2463x over previous
#include <cuda_runtime.h>
#include <math.h>

#define IMAGE_W 256
#define IMAGE_H 256
#define EPS 1e-7f
#define SIGMA2 0.02f

#define B 16
#define N 64
#define C 3
#define PH 32
#define PW 32
#define TILE 32
#define PSZ (C*PH*PW)   // 3072 floats per stroke patch

// Fused kernel: one block per (batch, 32x32 tile), 512 threads.
// Warp 0 computes stroke params + compacts tile survivors (1 barrier);
// then each thread gathers 1 col x 2 rows x 3 channels, direct predicated
// LDGs. Reg-capped to 32 (4 blocks/SM) with unroll-3 survivor loop.
__global__ void __launch_bounds__(512, 4) brush_kernel(
    const float* __restrict__ brushes,   // [B, N, 2]
    const float* __restrict__ patches,   // [B, N, 3, 32, 32]
    float* __restrict__ out)             // [B, 3, 256, 256]
{
    const int bt   = blockIdx.x;         // b*64 + tile
    const int b    = bt >> 6;
    const int tile = bt & 63;
    const int tx0  = (tile & 7) * TILE;
    const int ty0  = (tile >> 3) * TILE;
    const int tid  = threadIdx.x;
    const int lx   = tid & 31;
    const int g    = tid >> 5;           // 0..15

    __shared__ int4   cmeta[N];          // fx, fy, patch float-offset, pad
    __shared__ float4 cw[N];             // wx0, wx1, wy0/64, wy1/64
    __shared__ int    s_cnt;

    // ---- warp-0 prologue: params for 2 strokes/lane, ballot-compact ----
    if (tid < 32) {
        const int l = tid;
        const float2 br0 = ((const float2*)brushes)[b * N + l];
        const float2 br1 = ((const float2*)brushes)[b * N + l + 32];

        float mnx = fminf(br0.x, br1.x), mxx = fmaxf(br0.x, br1.x);
        float mny = fminf(br0.y, br1.y), mxy = fmaxf(br0.y, br1.y);
#pragma unroll
        for (int o = 16; o > 0; o >>= 1) {
            mnx = fminf(mnx, __shfl_xor_sync(0xffffffffu, mnx, o));
            mxx = fmaxf(mxx, __shfl_xor_sync(0xffffffffu, mxx, o));
            mny = fminf(mny, __shfl_xor_sync(0xffffffffu, mny, o));
            mxy = fmaxf(mxy, __shfl_xor_sync(0xffffffffu, mxy, o));
        }
        const float isx = 1.0f / (mxx - mnx + EPS) * (float)IMAGE_W;
        const float isy = 1.0f / (mxy - mny + EPS) * (float)IMAGE_H;

        int    fx[2], fy[2];
        float4 wt[2];
        bool   ov[2];
#pragma unroll
        for (int k = 0; k < 2; k++) {
            const float bx = k ? br1.x : br0.x;
            const float by = k ? br1.y : br0.y;
            const float axc = (bx - mnx) * isx - 15.5f;  // ux(q)=gx+q-15.5
            const float fx0f = floorf(axc);
            const float dx = axc - fx0f;
            const float ayc = (by - mny) * isy - 15.4f;  // uy(p)=gy+p-15.4
            const float fy0f = floorf(ayc);
            const float dy = ayc - fy0f;

            const float gx0 = __expf(-(dx * dx) / SIGMA2);
            const float gx1 = __expf(-((1.0f - dx) * (1.0f - dx)) / SIGMA2);
            const float wx0 = gx0 / (gx0 + gx1 + EPS);
            const float wx1 = gx1 / (gx0 + gx1 + EPS);

            const float gy0 = __expf(-(dy * dy) / SIGMA2);
            const float gy1 = __expf(-((1.0f - dy) * (1.0f - dy)) / SIGMA2);
            const float s  = 1.0f / 64.0f;               // fold /N into wy
            const float wy0 = gy0 / (gy0 + gy1 + EPS) * s;
            const float wy1 = gy1 / (gy0 + gy1 + EPS) * s;

            fx[k] = (int)fx0f;
            fy[k] = (int)fy0f;
            wt[k] = make_float4(wx0, wx1, wy0, wy1);
            ov[k] = !(fx[k] > tx0 + 31 || fx[k] + 32 < tx0 ||
                      fy[k] > ty0 + 31 || fy[k] + 32 < ty0);
        }

        const unsigned m0 = __ballot_sync(0xffffffffu, ov[0]);
        const unsigned m1 = __ballot_sync(0xffffffffu, ov[1]);
        const unsigned ltm = (1u << l) - 1u;
        const int base1 = __popc(m0);
        if (ov[0]) {
            const int pos = __popc(m0 & ltm);
            cmeta[pos] = make_int4(fx[0], fy[0], (b * N + l) * PSZ, 0);
            cw[pos]    = wt[0];
        }
        if (ov[1]) {
            const int pos = base1 + __popc(m1 & ltm);
            cmeta[pos] = make_int4(fx[1], fy[1], (b * N + l + 32) * PSZ, 0);
            cw[pos]    = wt[1];
        }
        if (l == 0) s_cnt = base1 + __popc(m1);
    }
    __syncthreads();
    const int cnt = s_cnt;

    // ---- gather ----
    const int x     = tx0 + lx;
    const int ybase = ty0 + g * 2;       // rows ybase, ybase+1

    float acc[C][2];
#pragma unroll
    for (int c = 0; c < C; c++) { acc[c][0] = 0.0f; acc[c][1] = 0.0f; }

#pragma unroll 3
    for (int s = 0; s < cnt; s++) {
        const int4   md = cmeta[s];
        const float4 wt = cw[s];
        const int i  = x - md.x;                   // window col
        const int jb = ybase - md.y;               // window row of first output
        if (jb < -1 || jb > 32) continue;          // warp-uniform skip
        const bool c0 = ((unsigned)i       < 32u); // tap col i
        const bool c1 = ((unsigned)(i - 1) < 32u); // tap col i-1
        const float* Pn = patches + md.z + i;
#pragma unroll
        for (int c = 0; c < C; c++) {
            const float* Pc = Pn + c * (PH * PW);
            float h[3];
#pragma unroll
            for (int r = 0; r < 3; r++) {
                const int rr = jb - 1 + r;
                const bool rv = ((unsigned)rr < 32u);
                const float p0 = (rv & c0) ? __ldg(Pc + rr * PW)     : 0.0f;
                const float p1 = (rv & c1) ? __ldg(Pc + rr * PW - 1) : 0.0f;
                h[r] = wt.x * p0 + wt.y * p1;
            }
            acc[c][0] += wt.z * h[1] + wt.w * h[0];
            acc[c][1] += wt.z * h[2] + wt.w * h[1];
        }
    }

    // ---- coalesced stores: [b][c][y][x] ----
#pragma unroll
    for (int c = 0; c < C; c++) {
        float* oc = out + ((size_t)(b * C + c) * IMAGE_H) * IMAGE_W;
        oc[(size_t)(ybase    ) * IMAGE_W + x] = acc[c][0];
        oc[(size_t)(ybase + 1) * IMAGE_W + x] = acc[c][1];
    }
}

extern "C" void kernel_launch(void* const* d_in, const int* in_sizes, int n_in,
                              void* d_out, int out_size)
{
    const float* brushes = (const float*)d_in[0];   // [16,64,2]
    const float* patches = (const float*)d_in[1];   // [16,64,3,32,32]
    float* out = (float*)d_out;                     // [16,3,256,256]

    brush_kernel<<<B * 64, 512>>>(brushes, patches, out);
}